// round 6
// baseline (speedup 1.0000x reference)
#include <cuda_runtime.h>
#include <math.h>

#define NN_MAX 50000
#define S_IN 128
#define S_OUT 128
#define K_MERGED 153
#define EPSS 1e-8f
#define NREP 8
#define TILE 16

// Scratch (static device globals)
__device__ float g_vdf[NN_MAX * 12];
__device__ float g_acc[(size_t)NREP * NN_MAX * 16];
__device__ float g_fold[NN_MAX * 12];
__device__ float g_WsoT[K_MERGED * 128];

// ---------------------------------------------------------------------------
// K1: zero replicated accumulators, compute vdf, transpose W_so
// ---------------------------------------------------------------------------
__global__ void k_pre(const float* __restrict__ vector,
                      const float* __restrict__ W_df,
                      const float* __restrict__ W_so,
                      int n_nodes)
{
    int tid = blockIdx.x * blockDim.x + threadIdx.x;

    size_t nzero4 = (size_t)NREP * n_nodes * 4;
    if ((size_t)tid < nzero4)
        reinterpret_cast<float4*>(g_acc)[tid] = make_float4(0.f, 0.f, 0.f, 0.f);

    if (tid < K_MERGED * 128) {
        int k = tid >> 7, o = tid & 127;
        g_WsoT[tid] = W_so[o * K_MERGED + k];
    }

    if (tid >= n_nodes) return;
    int n = tid;

    float v[48];
    const float4* vp = reinterpret_cast<const float4*>(vector + (size_t)n * 48);
#pragma unroll
    for (int q = 0; q < 12; q++) {
        float4 f = vp[q];
        v[q*4+0] = f.x; v[q*4+1] = f.y; v[q*4+2] = f.z; v[q*4+3] = f.w;
    }
#pragma unroll
    for (int j = 0; j < 3; j++) {
        float r0 = 0.f, r1 = 0.f, r2 = 0.f;
#pragma unroll
        for (int i = 0; i < 16; i++) {
            float x = v[i*3 + j];
            r0 += x * __ldg(&W_df[i]);
            r1 += x * __ldg(&W_df[16 + i]);
            r2 += x * __ldg(&W_df[32 + i]);
        }
        g_vdf[(size_t)n*12 + j*3 + 0] = r0;
        g_vdf[(size_t)n*12 + j*3 + 1] = r1;
        g_vdf[(size_t)n*12 + j*3 + 2] = r2;
    }
}

// ---------------------------------------------------------------------------
// K2: per-edge rotation + replicated scatter-add (replica = e & 7)
// ---------------------------------------------------------------------------
__global__ void k_edge(const int* __restrict__ ei,
                       const float* __restrict__ frames,
                       int n_edges, int n_nodes)
{
    int e = blockIdx.x * blockDim.x + threadIdx.x;
    if (e >= n_edges) return;

    int row = ei[e];

    const float4* vp = reinterpret_cast<const float4*>(g_vdf + (size_t)row * 12);
    float4 va = vp[0], vb = vp[1], vc = vp[2];
    float v[9] = { va.x, va.y, va.z, va.w, vb.x, vb.y, vb.z, vb.w, vc.x };

    const float* f = frames + (size_t)e * 9;
    float F[9];
#pragma unroll
    for (int i = 0; i < 9; i++) F[i] = __ldg(&f[i]);

    float loc[9];
#pragma unroll
    for (int x = 0; x < 3; x++)
#pragma unroll
        for (int c = 0; c < 3; c++)
            loc[c*3 + x] = F[x*3+0]*v[0+c] + F[x*3+1]*v[3+c] + F[x*3+2]*v[6+c];

    int rep = e & (NREP - 1);
    float* dst = g_acc + ((size_t)rep * n_nodes + row) * 16;
    asm volatile("red.global.add.v4.f32 [%0], {%1,%2,%3,%4};" ::
                 "l"(dst), "f"(loc[0]), "f"(loc[1]), "f"(loc[2]), "f"(loc[3]) : "memory");
    asm volatile("red.global.add.v4.f32 [%0], {%1,%2,%3,%4};" ::
                 "l"(dst+4), "f"(loc[4]), "f"(loc[5]), "f"(loc[6]), "f"(loc[7]) : "memory");
    asm volatile("red.global.add.v2.f32 [%0], {%1,%2};" ::
                 "l"(dst+8), "f"(loc[8]), "f"(1.0f) : "memory");
}

// ---------------------------------------------------------------------------
// K2b: fold replicas -> meaned 9 values per node
// ---------------------------------------------------------------------------
__global__ void k_fold(int n_nodes)
{
    int n = blockIdx.x * blockDim.x + threadIdx.x;
    if (n >= n_nodes) return;

    float sum[9] = {0,0,0,0,0,0,0,0,0};
    float cnt = 0.f;
#pragma unroll
    for (int r = 0; r < NREP; r++) {
        const float* a = g_acc + ((size_t)r * n_nodes + n) * 16;
        float4 p0 = reinterpret_cast<const float4*>(a)[0];
        float4 p1 = reinterpret_cast<const float4*>(a)[1];
        float2 p2 = reinterpret_cast<const float2*>(a)[4];
        sum[0] += p0.x; sum[1] += p0.y; sum[2] += p0.z; sum[3] += p0.w;
        sum[4] += p1.x; sum[5] += p1.y; sum[6] += p1.z; sum[7] += p1.w;
        sum[8] += p2.x; cnt += p2.y;
    }
    float inv = 1.0f / fmaxf(cnt, 1.0f);
    float* o = g_fold + (size_t)n * 12;
#pragma unroll
    for (int c = 0; c < 9; c++) o[c] = sum[c] * inv;
    o[9] = 0.f; o[10] = 0.f; o[11] = 0.f;
}

// ---------------------------------------------------------------------------
// K3: node MLP. 256 threads, split-K GEMM (each half-block owns 38 k-pairs),
// 16-node tiles, f32x2 FMA, v2.u64 shared loads, 32 warps/SM.
// merged row per node: [0:128) scalar, [128:144) vnorm, [144:153) sh; pad 156.
// ---------------------------------------------------------------------------
__global__ __launch_bounds__(256, 2) void k_post(
    const float* __restrict__ scalar, const float* __restrict__ vector,
    const float* __restrict__ W_down, const float* __restrict__ b_so,
    const float* __restrict__ W_up, const float* __restrict__ W_g,
    const float* __restrict__ b_g,
    float* __restrict__ out_s, float* __restrict__ out_v, int n_nodes)
{
    const int t = threadIdx.x;
    const int col = t & 127;
    const int half = t >> 7;

    // this thread's 38 W_so k-pairs (k = half*76 .. half*76+75, paired)
    unsigned long long ww[38];
#pragma unroll
    for (int kp = 0; kp < 38; kp++) {
        int kk = half * 38 + kp;
        float w0 = g_WsoT[(2*kk)   * 128 + col];
        float w1 = g_WsoT[(2*kk+1) * 128 + col];
        asm("mov.b64 %0, {%1, %2};" : "=l"(ww[kp]) : "f"(w0), "f"(w1));
    }
    const float wlast = g_WsoT[152 * 128 + col];
    const float bso = b_so[col];

    // gates: output go = t>>4 (0..15), partial gpart = t&15 over 8 k's
    const int go = t >> 4, gpart = t & 15;
    float wg[8];
#pragma unroll
    for (int k = 0; k < 8; k++) wg[k] = W_g[go * 128 + gpart * 8 + k];
    const float bg = b_g[go];

    __shared__ __align__(16) float mbuf[TILE * 156];
    __shared__ float pbuf[2][TILE * 128];
    __shared__ float vecs[TILE][49];
    __shared__ float vh[TILE][49];
    __shared__ float ssm[TILE][128];
    __shared__ float gsig[TILE][16];
    __shared__ float sWdown[256], sWup[256];

    sWdown[t] = W_down[t];
    sWup[t] = W_up[t];
    __syncthreads();

    const int ntiles = (n_nodes + TILE - 1) / TILE;

    for (int tile = blockIdx.x; tile < ntiles; tile += gridDim.x) {
        const int nb = tile * TILE;

        // ---- Phase A: loads ----
#pragma unroll
        for (int r = 0; r < 8; r++) {
            int nd = half + r * 2;
            int node = nb + nd;
            float p = (node < n_nodes) ? scalar[(size_t)node * 128 + col] : 0.f;
            mbuf[nd * 156 + col] = p;
        }
        if (t < 192) {
            int nd = t / 12, qq = t - nd * 12;
            int node = nb + nd;
            float4 f = (node < n_nodes)
                ? reinterpret_cast<const float4*>(vector)[(size_t)node * 12 + qq]
                : make_float4(0.f,0.f,0.f,0.f);
            int c = qq * 4;
            vecs[nd][c] = f.x; vecs[nd][c+1] = f.y; vecs[nd][c+2] = f.z; vecs[nd][c+3] = f.w;
        }
        if (t < 48) {
            int nd = t / 3, q = t - nd * 3;
            int node = nb + nd;
            float4 f = (node < n_nodes)
                ? reinterpret_cast<const float4*>(g_fold)[(size_t)node * 3 + q]
                : make_float4(0.f,0.f,0.f,0.f);
            int c = q * 4;
            float vv[4] = { f.x, f.y, f.z, f.w };
#pragma unroll
            for (int j = 0; j < 4; j++)
                if (c + j < 9) mbuf[nd * 156 + 144 + c + j] = vv[j];
        }
        __syncthreads();

        // ---- Phase B: vh + vnorm (nd = t>>4, h = t&15) ----
        {
            int nd = t >> 4, h = t & 15;
            float a0 = 0.f, a1 = 0.f, a2 = 0.f;
#pragma unroll
            for (int i = 0; i < 16; i++) {
                float wd = sWdown[h * 16 + i];
                a0 += vecs[nd][i*3 + 0] * wd;
                a1 += vecs[nd][i*3 + 1] * wd;
                a2 += vecs[nd][i*3 + 2] * wd;
            }
            vh[nd][0*16 + h] = a0;
            vh[nd][1*16 + h] = a1;
            vh[nd][2*16 + h] = a2;
            mbuf[nd * 156 + 128 + h] = sqrtf(a0*a0 + a1*a1 + a2*a2 + EPSS);
        }
        __syncthreads();

        // ---- Phase C: split-K GEMM, two passes of 8 nodes ----
        {
            const ulonglong2* mp = reinterpret_cast<const ulonglong2*>(mbuf);
            const int vbase = half * 19;   // 19 v2 loads cover this half's 38 pairs
#pragma unroll
            for (int pass = 0; pass < 2; pass++) {
                unsigned long long acc[8];
#pragma unroll
                for (int i = 0; i < 8; i++) acc[i] = 0ULL;
#pragma unroll 2
                for (int kq = 0; kq < 19; kq++) {
                    unsigned long long w0 = ww[2*kq], w1 = ww[2*kq + 1];
#pragma unroll
                    for (int i = 0; i < 8; i++) {
                        int nd = pass * 8 + i;
                        ulonglong2 m = mp[nd * 39 + vbase + kq];
                        asm("fma.rn.f32x2 %0, %1, %2, %0;" : "+l"(acc[i]) : "l"(w0), "l"(m.x));
                        asm("fma.rn.f32x2 %0, %1, %2, %0;" : "+l"(acc[i]) : "l"(w1), "l"(m.y));
                    }
                }
#pragma unroll
                for (int i = 0; i < 8; i++) {
                    int nd = pass * 8 + i;
                    float lo, hi;
                    asm("mov.b64 {%0, %1}, %2;" : "=f"(lo), "=f"(hi) : "l"(acc[i]));
                    pbuf[half][nd * 128 + col] = lo + hi;
                }
            }
        }
        __syncthreads();

        // ---- combine halves: each half finalizes 8 nodes ----
        {
            int base = half * 8;
#pragma unroll
            for (int i = 0; i < 8; i++) {
                int nd = base + i;
                float sv = pbuf[0][nd * 128 + col] + pbuf[1][nd * 128 + col]
                         + bso + wlast * mbuf[nd * 156 + 152];
                float sil = sv / (1.0f + __expf(-sv));
                ssm[nd][col] = sil;
                int node = nb + nd;
                if (node < n_nodes)
                    out_s[(size_t)node * 128 + col] = sil;
            }
        }
        __syncthreads();

        // ---- Phase D: gates (16 threads per output, 16-lane shfl reduce) ----
#pragma unroll
        for (int nd = 0; nd < TILE; nd++) {
            float p = 0.f;
#pragma unroll
            for (int k = 0; k < 8; k++)
                p += ssm[nd][gpart * 8 + k] * wg[k];
            p += __shfl_xor_sync(0xFFFFFFFFu, p, 1);
            p += __shfl_xor_sync(0xFFFFFFFFu, p, 2);
            p += __shfl_xor_sync(0xFFFFFFFFu, p, 4);
            p += __shfl_xor_sync(0xFFFFFFFFu, p, 8);
            if (gpart == 0)
                gsig[nd][go] = 1.0f / (1.0f + __expf(-(p + bg)));
        }
        __syncthreads();

        // ---- Phase E: gated vector output (768 items, 3 per thread) ----
#pragma unroll
        for (int r = 0; r < 3; r++) {
            int i = t + 256 * r;
            int nd = i / 48, j = i - nd * 48;
            int o = j / 3, x = j - o * 3;
            float a = 0.f;
#pragma unroll
            for (int h = 0; h < 16; h++)
                a += vh[nd][x*16 + h] * sWup[o*16 + h];
            int node = nb + nd;
            if (node < n_nodes)
                out_v[(size_t)node * 48 + j] = a * gsig[nd][o];
        }
        __syncthreads();
    }
}

extern "C" void kernel_launch(void* const* d_in, const int* in_sizes, int n_in,
                              void* d_out, int out_size) {
    const float* scalar = (const float*)d_in[0];
    const float* vector = (const float*)d_in[1];
    const int*   ei     = (const int*)d_in[2];
    const float* frames = (const float*)d_in[3];
    const float* W_down = (const float*)d_in[4];
    const float* W_df   = (const float*)d_in[5];
    const float* W_so   = (const float*)d_in[6];
    const float* b_so   = (const float*)d_in[7];
    const float* W_up   = (const float*)d_in[8];
    const float* W_g    = (const float*)d_in[9];
    const float* b_g    = (const float*)d_in[10];

    int n = in_sizes[0] / S_IN;
    int e = in_sizes[2] / 2;

    float* out_s = (float*)d_out;
    float* out_v = out_s + (size_t)n * S_OUT;

    size_t pre_jobs = (size_t)NREP * n * 4;
    if (pre_jobs < (size_t)n) pre_jobs = n;
    if (pre_jobs < (size_t)K_MERGED * 128) pre_jobs = K_MERGED * 128;

    k_pre<<<(int)((pre_jobs + 255) / 256), 256>>>(vector, W_df, W_so, n);
    k_edge<<<(e + 255) / 256, 256>>>(ei, frames, e, n);
    k_fold<<<(n + 255) / 256, 256>>>(n);
    k_post<<<296, 256>>>(scalar, vector, W_down, b_so, W_up, W_g, b_g,
                         out_s, out_v, n);
}

// round 7
// speedup vs baseline: 1.0515x; 1.0515x over previous
#include <cuda_runtime.h>
#include <math.h>

#define NN_MAX 50000
#define S_IN 128
#define S_OUT 128
#define K_MERGED 153
#define EPSS 1e-8f
#define NREP 8
#define TILE 32

// Scratch (static device globals)
__device__ float g_vdf[NN_MAX * 12];
__device__ float g_acc[(size_t)NREP * NN_MAX * 16];
__device__ float g_fold[NN_MAX * 12];
__device__ float g_WsoT[K_MERGED * 128];   // [k][col]

// ---------------------------------------------------------------------------
// K1: zero replicated accumulators, compute vdf, transpose W_so
// ---------------------------------------------------------------------------
__global__ void k_pre(const float* __restrict__ vector,
                      const float* __restrict__ W_df,
                      const float* __restrict__ W_so,
                      int n_nodes)
{
    int tid = blockIdx.x * blockDim.x + threadIdx.x;

    size_t nzero4 = (size_t)NREP * n_nodes * 4;
    if ((size_t)tid < nzero4)
        reinterpret_cast<float4*>(g_acc)[tid] = make_float4(0.f, 0.f, 0.f, 0.f);

    if (tid < K_MERGED * 128) {
        int k = tid >> 7, o = tid & 127;
        g_WsoT[tid] = W_so[o * K_MERGED + k];
    }

    if (tid >= n_nodes) return;
    int n = tid;

    float v[48];
    const float4* vp = reinterpret_cast<const float4*>(vector + (size_t)n * 48);
#pragma unroll
    for (int q = 0; q < 12; q++) {
        float4 f = vp[q];
        v[q*4+0] = f.x; v[q*4+1] = f.y; v[q*4+2] = f.z; v[q*4+3] = f.w;
    }
#pragma unroll
    for (int j = 0; j < 3; j++) {
        float r0 = 0.f, r1 = 0.f, r2 = 0.f;
#pragma unroll
        for (int i = 0; i < 16; i++) {
            float x = v[i*3 + j];
            r0 += x * __ldg(&W_df[i]);
            r1 += x * __ldg(&W_df[16 + i]);
            r2 += x * __ldg(&W_df[32 + i]);
        }
        g_vdf[(size_t)n*12 + j*3 + 0] = r0;
        g_vdf[(size_t)n*12 + j*3 + 1] = r1;
        g_vdf[(size_t)n*12 + j*3 + 2] = r2;
    }
}

// ---------------------------------------------------------------------------
// K2: per-edge rotation + replicated scatter-add (replica = e & 7)
// ---------------------------------------------------------------------------
__global__ void k_edge(const int* __restrict__ ei,
                       const float* __restrict__ frames,
                       int n_edges, int n_nodes)
{
    int e = blockIdx.x * blockDim.x + threadIdx.x;
    if (e >= n_edges) return;

    int row = ei[e];

    const float4* vp = reinterpret_cast<const float4*>(g_vdf + (size_t)row * 12);
    float4 va = vp[0], vb = vp[1], vc = vp[2];
    float v[9] = { va.x, va.y, va.z, va.w, vb.x, vb.y, vb.z, vb.w, vc.x };

    const float* f = frames + (size_t)e * 9;
    float F[9];
#pragma unroll
    for (int i = 0; i < 9; i++) F[i] = __ldg(&f[i]);

    float loc[9];
#pragma unroll
    for (int x = 0; x < 3; x++)
#pragma unroll
        for (int c = 0; c < 3; c++)
            loc[c*3 + x] = F[x*3+0]*v[0+c] + F[x*3+1]*v[3+c] + F[x*3+2]*v[6+c];

    int rep = e & (NREP - 1);
    float* dst = g_acc + ((size_t)rep * n_nodes + row) * 16;
    asm volatile("red.global.add.v4.f32 [%0], {%1,%2,%3,%4};" ::
                 "l"(dst), "f"(loc[0]), "f"(loc[1]), "f"(loc[2]), "f"(loc[3]) : "memory");
    asm volatile("red.global.add.v4.f32 [%0], {%1,%2,%3,%4};" ::
                 "l"(dst+4), "f"(loc[4]), "f"(loc[5]), "f"(loc[6]), "f"(loc[7]) : "memory");
    asm volatile("red.global.add.v2.f32 [%0], {%1,%2};" ::
                 "l"(dst+8), "f"(loc[8]), "f"(1.0f) : "memory");
}

// ---------------------------------------------------------------------------
// K2b: fold replicas -> meaned 9 values per node
// ---------------------------------------------------------------------------
__global__ void k_fold(int n_nodes)
{
    int n = blockIdx.x * blockDim.x + threadIdx.x;
    if (n >= n_nodes) return;

    float sum[9] = {0,0,0,0,0,0,0,0,0};
    float cnt = 0.f;
#pragma unroll
    for (int r = 0; r < NREP; r++) {
        const float* a = g_acc + ((size_t)r * n_nodes + n) * 16;
        float4 p0 = reinterpret_cast<const float4*>(a)[0];
        float4 p1 = reinterpret_cast<const float4*>(a)[1];
        float2 p2 = reinterpret_cast<const float2*>(a)[4];
        sum[0] += p0.x; sum[1] += p0.y; sum[2] += p0.z; sum[3] += p0.w;
        sum[4] += p1.x; sum[5] += p1.y; sum[6] += p1.z; sum[7] += p1.w;
        sum[8] += p2.x; cnt += p2.y;
    }
    float inv = 1.0f / fmaxf(cnt, 1.0f);
    float* o = g_fold + (size_t)n * 12;
#pragma unroll
    for (int c = 0; c < 9; c++) o[c] = sum[c] * inv;
    o[9] = 0.f; o[10] = 0.f; o[11] = 0.f;
}

// ---------------------------------------------------------------------------
// K3: node MLP. 32-node tiles, outer-product GEMM: thread owns 4 cols x 4
// nodes; weights via LDG.128 (L1-resident g_WsoT), merged k-major in smem,
// f32x2 FMAs. No weight registers -> 3 CTAs/SM.
// mT[k][nd] rows: k 0..127 scalar, 128..143 vnorm, 144..152 sh. Row pad 36.
// ---------------------------------------------------------------------------
__global__ __launch_bounds__(256, 3) void k_post(
    const float* __restrict__ scalar, const float* __restrict__ vector,
    const float* __restrict__ W_down, const float* __restrict__ b_so,
    const float* __restrict__ W_up, const float* __restrict__ W_g,
    const float* __restrict__ b_g,
    float* __restrict__ out_s, float* __restrict__ out_v, int n_nodes)
{
    const int t = threadIdx.x;
    const int lane = t & 31;
    const int wid = t >> 5;
    const int col4 = lane * 4;      // GEMM cols col4..col4+3
    const int nd0 = wid * 4;        // GEMM nodes nd0..nd0+3

    // biases for my 4 cols
    const float4 bso = *reinterpret_cast<const float4*>(b_so + col4);

    // gates: output go = t>>4, partial gpart = t&15 over 8 k's
    const int go = t >> 4, gpart = t & 15;
    float wg[8];
#pragma unroll
    for (int k = 0; k < 8; k++) wg[k] = W_g[go * 128 + gpart * 8 + k];
    const float bg = b_g[go];

    __shared__ __align__(16) float mT[K_MERGED * 36];   // 22032 B
    __shared__ __align__(16) float uni[TILE * 128];     // ssm  ∪  vecs[32][52]
    __shared__ float vh[TILE * 50];
    __shared__ float gsig[TILE * 16];
    __shared__ float sWdown[256], sWup[256];

    float* const ssm  = uni;   // [nd*128 + col], phases C..D
    float* const vecs = uni;   // [nd*52 + c],    phases A..B

    sWdown[t] = W_down[t];
    sWup[t]   = W_up[t];
    __syncthreads();

    const int ntiles = (n_nodes + TILE - 1) / TILE;
    const int acol = t >> 1, asub = t & 1;

    for (int tile = blockIdx.x; tile < ntiles; tile += gridDim.x) {
        const int nb = tile * TILE;

        // ================= Phase A: build mT scalar rows, vecs, sh =========
#pragma unroll 4
        for (int i = 0; i < 16; i++) {
            int nd = asub * 16 + i;
            int node = nb + nd;
            float p = (node < n_nodes) ? scalar[(size_t)node * 128 + acol] : 0.f;
            mT[acol * 36 + nd] = p;
        }
#pragma unroll
        for (int r = 0; r < 2; r++) {
            int idx = t + 256 * r;
            if (idx < 384) {
                int nd = idx / 12, q = idx - nd * 12;
                int node = nb + nd;
                float4 f = (node < n_nodes)
                    ? reinterpret_cast<const float4*>(vector)[(size_t)node * 12 + q]
                    : make_float4(0.f, 0.f, 0.f, 0.f);
                *reinterpret_cast<float4*>(vecs + nd * 52 + q * 4) = f;
            }
        }
        {
            int nd = t & 31, node = nb + nd;
            for (int c = t >> 5; c < 9; c += 8) {
                float v = (node < n_nodes) ? g_fold[(size_t)node * 12 + c] : 0.f;
                mT[(144 + c) * 36 + nd] = v;
            }
        }
        __syncthreads();

        // ================= Phase B: vh + vnorm rows =========================
        {
            int nd = t >> 3, h2 = (t & 7) * 2;
#pragma unroll
            for (int hh = 0; hh < 2; hh++) {
                int h = h2 + hh;
                float a0 = 0.f, a1 = 0.f, a2 = 0.f;
#pragma unroll
                for (int i = 0; i < 16; i++) {
                    float wd = sWdown[h * 16 + i];
                    a0 += vecs[nd * 52 + i * 3 + 0] * wd;
                    a1 += vecs[nd * 52 + i * 3 + 1] * wd;
                    a2 += vecs[nd * 52 + i * 3 + 2] * wd;
                }
                vh[nd * 50 +  0 + h] = a0;
                vh[nd * 50 + 16 + h] = a1;
                vh[nd * 50 + 32 + h] = a2;
                mT[(128 + h) * 36 + nd] = sqrtf(a0*a0 + a1*a1 + a2*a2 + EPSS);
            }
        }
        __syncthreads();

        // ================= Phase C: outer-product GEMM ======================
        {
            unsigned long long a00=0ULL,a01=0ULL,a10=0ULL,a11=0ULL,
                               a20=0ULL,a21=0ULL,a30=0ULL,a31=0ULL;
            const float* wbase = g_WsoT + col4;
            const float* mbase = mT + nd0;
#pragma unroll 3
            for (int k = 0; k < K_MERGED; k++) {
                float4 w = __ldg(reinterpret_cast<const float4*>(wbase + k * 128));
                ulonglong2 m = *reinterpret_cast<const ulonglong2*>(mbase + k * 36);
                unsigned long long wd0, wd1, wd2, wd3;
                asm("mov.b64 %0, {%1, %1};" : "=l"(wd0) : "f"(w.x));
                asm("mov.b64 %0, {%1, %1};" : "=l"(wd1) : "f"(w.y));
                asm("mov.b64 %0, {%1, %1};" : "=l"(wd2) : "f"(w.z));
                asm("mov.b64 %0, {%1, %1};" : "=l"(wd3) : "f"(w.w));
                asm("fma.rn.f32x2 %0, %1, %2, %0;" : "+l"(a00) : "l"(wd0), "l"(m.x));
                asm("fma.rn.f32x2 %0, %1, %2, %0;" : "+l"(a01) : "l"(wd0), "l"(m.y));
                asm("fma.rn.f32x2 %0, %1, %2, %0;" : "+l"(a10) : "l"(wd1), "l"(m.x));
                asm("fma.rn.f32x2 %0, %1, %2, %0;" : "+l"(a11) : "l"(wd1), "l"(m.y));
                asm("fma.rn.f32x2 %0, %1, %2, %0;" : "+l"(a20) : "l"(wd2), "l"(m.x));
                asm("fma.rn.f32x2 %0, %1, %2, %0;" : "+l"(a21) : "l"(wd2), "l"(m.y));
                asm("fma.rn.f32x2 %0, %1, %2, %0;" : "+l"(a30) : "l"(wd3), "l"(m.x));
                asm("fma.rn.f32x2 %0, %1, %2, %0;" : "+l"(a31) : "l"(wd3), "l"(m.y));
            }
            // epilogue: unpack, silu, stage to ssm
            unsigned long long accs[8] = {a00,a01,a10,a11,a20,a21,a30,a31};
            float bb[4] = { bso.x, bso.y, bso.z, bso.w };
#pragma unroll
            for (int c = 0; c < 4; c++) {
#pragma unroll
                for (int p = 0; p < 2; p++) {
                    float lo, hi;
                    asm("mov.b64 {%0, %1}, %2;" : "=f"(lo), "=f"(hi) : "l"(accs[c*2+p]));
                    float sv0 = lo + bb[c];
                    float sv1 = hi + bb[c];
                    float s0 = sv0 / (1.0f + __expf(-sv0));
                    float s1 = sv1 / (1.0f + __expf(-sv1));
                    ssm[(nd0 + 2*p    ) * 128 + col4 + c] = s0;
                    ssm[(nd0 + 2*p + 1) * 128 + col4 + c] = s1;
                }
            }
        }
        __syncthreads();

        // ================= Phase D: gates + out_s write =====================
#pragma unroll 4
        for (int nd = 0; nd < TILE; nd++) {
            float p = 0.f;
#pragma unroll
            for (int k = 0; k < 8; k++)
                p += ssm[nd * 128 + gpart * 8 + k] * wg[k];
            p += __shfl_xor_sync(0xFFFFFFFFu, p, 1);
            p += __shfl_xor_sync(0xFFFFFFFFu, p, 2);
            p += __shfl_xor_sync(0xFFFFFFFFu, p, 4);
            p += __shfl_xor_sync(0xFFFFFFFFu, p, 8);
            if (gpart == 0)
                gsig[nd * 16 + go] = 1.0f / (1.0f + __expf(-(p + bg)));
        }
#pragma unroll
        for (int r = 0; r < 4; r++) {
            int nd = (t >> 5) + 8 * r;
            int node = nb + nd;
            float4 v = *reinterpret_cast<const float4*>(ssm + nd * 128 + col4);
            if (node < n_nodes)
                reinterpret_cast<float4*>(out_s + (size_t)node * 128)[lane] = v;
        }
        __syncthreads();

        // ================= Phase E: gated vector output =====================
#pragma unroll
        for (int r = 0; r < 6; r++) {
            int i = t + 256 * r;
            int nd = i / 48, j = i - nd * 48;
            int o = j / 3, x = j - o * 3;
            float a = 0.f;
#pragma unroll
            for (int h = 0; h < 16; h++)
                a += vh[nd * 50 + x * 16 + h] * sWup[o * 16 + h];
            int node = nb + nd;
            if (node < n_nodes)
                out_v[(size_t)node * 48 + j] = a * gsig[nd * 16 + o];
        }
        __syncthreads();
    }
}

extern "C" void kernel_launch(void* const* d_in, const int* in_sizes, int n_in,
                              void* d_out, int out_size) {
    const float* scalar = (const float*)d_in[0];
    const float* vector = (const float*)d_in[1];
    const int*   ei     = (const int*)d_in[2];
    const float* frames = (const float*)d_in[3];
    const float* W_down = (const float*)d_in[4];
    const float* W_df   = (const float*)d_in[5];
    const float* W_so   = (const float*)d_in[6];
    const float* b_so   = (const float*)d_in[7];
    const float* W_up   = (const float*)d_in[8];
    const float* W_g    = (const float*)d_in[9];
    const float* b_g    = (const float*)d_in[10];

    int n = in_sizes[0] / S_IN;
    int e = in_sizes[2] / 2;

    float* out_s = (float*)d_out;
    float* out_v = out_s + (size_t)n * S_OUT;

    size_t pre_jobs = (size_t)NREP * n * 4;
    if (pre_jobs < (size_t)n) pre_jobs = n;
    if (pre_jobs < (size_t)K_MERGED * 128) pre_jobs = K_MERGED * 128;

    k_pre<<<(int)((pre_jobs + 255) / 256), 256>>>(vector, W_df, W_so, n);
    k_edge<<<(e + 255) / 256, 256>>>(ei, frames, e, n);
    k_fold<<<(n + 255) / 256, 256>>>(n);
    k_post<<<444, 256>>>(scalar, vector, W_down, b_so, W_up, W_g, b_g,
                         out_s, out_v, n);
}

// round 8
// speedup vs baseline: 1.1848x; 1.1269x over previous
#include <cuda_runtime.h>
#include <math.h>

#define NN_MAX 50000
#define S_IN 128
#define S_OUT 128
#define K_MERGED 153
#define EPSS 1e-8f
#define NREP 8
#define TILE 32
#define MROW 68   // mT2 row pad (floats), multiple of 4

// Scratch (static device globals)
__device__ float g_vdf[NN_MAX * 12];
__device__ float g_acc[(size_t)NREP * NN_MAX * 16];
__device__ float g_fold[NN_MAX * 12];
__device__ float g_WsoT[K_MERGED * 128];   // [k][col]
__device__ float g_WgT[128 * 16];          // blocked: [k4][o][kk], k=k4*4+kk

// ---------------------------------------------------------------------------
// K1: zero accumulators, compute vdf, transpose W_so and W_g
// ---------------------------------------------------------------------------
__global__ void k_pre(const float* __restrict__ vector,
                      const float* __restrict__ W_df,
                      const float* __restrict__ W_so,
                      const float* __restrict__ W_g,
                      int n_nodes)
{
    int tid = blockIdx.x * blockDim.x + threadIdx.x;

    size_t nzero4 = (size_t)NREP * n_nodes * 4;
    if ((size_t)tid < nzero4)
        reinterpret_cast<float4*>(g_acc)[tid] = make_float4(0.f, 0.f, 0.f, 0.f);

    if (tid < K_MERGED * 128) {
        int k = tid >> 7, o = tid & 127;
        g_WsoT[tid] = W_so[o * K_MERGED + k];
    }
    if (tid < 2048) {
        int kk = tid & 3, o = (tid >> 2) & 15, k4 = tid >> 6;
        g_WgT[tid] = W_g[o * 128 + k4 * 4 + kk];
    }

    if (tid >= n_nodes) return;
    int n = tid;

    float v[48];
    const float4* vp = reinterpret_cast<const float4*>(vector + (size_t)n * 48);
#pragma unroll
    for (int q = 0; q < 12; q++) {
        float4 f = vp[q];
        v[q*4+0] = f.x; v[q*4+1] = f.y; v[q*4+2] = f.z; v[q*4+3] = f.w;
    }
#pragma unroll
    for (int j = 0; j < 3; j++) {
        float r0 = 0.f, r1 = 0.f, r2 = 0.f;
#pragma unroll
        for (int i = 0; i < 16; i++) {
            float x = v[i*3 + j];
            r0 += x * __ldg(&W_df[i]);
            r1 += x * __ldg(&W_df[16 + i]);
            r2 += x * __ldg(&W_df[32 + i]);
        }
        g_vdf[(size_t)n*12 + j*3 + 0] = r0;
        g_vdf[(size_t)n*12 + j*3 + 1] = r1;
        g_vdf[(size_t)n*12 + j*3 + 2] = r2;
    }
}

// ---------------------------------------------------------------------------
// K2: per-edge rotation + replicated scatter-add (replica = e & 7)
// ---------------------------------------------------------------------------
__global__ void k_edge(const int* __restrict__ ei,
                       const float* __restrict__ frames,
                       int n_edges, int n_nodes)
{
    int e = blockIdx.x * blockDim.x + threadIdx.x;
    if (e >= n_edges) return;

    int row = ei[e];

    const float4* vp = reinterpret_cast<const float4*>(g_vdf + (size_t)row * 12);
    float4 va = vp[0], vb = vp[1], vc = vp[2];
    float v[9] = { va.x, va.y, va.z, va.w, vb.x, vb.y, vb.z, vb.w, vc.x };

    const float* f = frames + (size_t)e * 9;
    float F[9];
#pragma unroll
    for (int i = 0; i < 9; i++) F[i] = __ldg(&f[i]);

    float loc[9];
#pragma unroll
    for (int x = 0; x < 3; x++)
#pragma unroll
        for (int c = 0; c < 3; c++)
            loc[c*3 + x] = F[x*3+0]*v[0+c] + F[x*3+1]*v[3+c] + F[x*3+2]*v[6+c];

    int rep = e & (NREP - 1);
    float* dst = g_acc + ((size_t)rep * n_nodes + row) * 16;
    asm volatile("red.global.add.v4.f32 [%0], {%1,%2,%3,%4};" ::
                 "l"(dst), "f"(loc[0]), "f"(loc[1]), "f"(loc[2]), "f"(loc[3]) : "memory");
    asm volatile("red.global.add.v4.f32 [%0], {%1,%2,%3,%4};" ::
                 "l"(dst+4), "f"(loc[4]), "f"(loc[5]), "f"(loc[6]), "f"(loc[7]) : "memory");
    asm volatile("red.global.add.v2.f32 [%0], {%1,%2};" ::
                 "l"(dst+8), "f"(loc[8]), "f"(1.0f) : "memory");
}

// ---------------------------------------------------------------------------
// K2b: fold replicas -> meaned 9 values per node
// ---------------------------------------------------------------------------
__global__ void k_fold(int n_nodes)
{
    int n = blockIdx.x * blockDim.x + threadIdx.x;
    if (n >= n_nodes) return;

    float sum[9] = {0,0,0,0,0,0,0,0,0};
    float cnt = 0.f;
#pragma unroll
    for (int r = 0; r < NREP; r++) {
        const float* a = g_acc + ((size_t)r * n_nodes + n) * 16;
        float4 p0 = reinterpret_cast<const float4*>(a)[0];
        float4 p1 = reinterpret_cast<const float4*>(a)[1];
        float2 p2 = reinterpret_cast<const float2*>(a)[4];
        sum[0] += p0.x; sum[1] += p0.y; sum[2] += p0.z; sum[3] += p0.w;
        sum[4] += p1.x; sum[5] += p1.y; sum[6] += p1.z; sum[7] += p1.w;
        sum[8] += p2.x; cnt += p2.y;
    }
    float inv = 1.0f / fmaxf(cnt, 1.0f);
    float* o = g_fold + (size_t)n * 12;
#pragma unroll
    for (int c = 0; c < 9; c++) o[c] = sum[c] * inv;
    o[9] = 0.f; o[10] = 0.f; o[11] = 0.f;
}

// ---------------------------------------------------------------------------
// K3: node MLP. 32-node tiles; merged stored PRE-DUPLICATED (f32 pairs) in
// smem -> zero-MOV f32x2 outer-product GEMM (11 SASS/k). Gates via blocked
// transposed weights, conflict-free, shuffle-free.
// ---------------------------------------------------------------------------
__global__ __launch_bounds__(256, 3) void k_post(
    const float* __restrict__ scalar, const float* __restrict__ vector,
    const float* __restrict__ W_down, const float* __restrict__ b_so,
    const float* __restrict__ W_up,
    const float* __restrict__ b_g,
    float* __restrict__ out_s, float* __restrict__ out_v, int n_nodes)
{
    const int t = threadIdx.x;
    const int lane = t & 31;
    const int wid = t >> 5;
    const int col4 = lane * 4;      // GEMM cols col4..col4+3
    const int nd0 = wid * 4;        // GEMM nodes nd0..nd0+3

    const float4 bso = *reinterpret_cast<const float4*>(b_so + col4);

    // gates: o = t&15; this thread does nodes ndA = t>>4 and ndA+16
    const int go = t & 15;
    const int ndA = t >> 4;
    const float bg = b_g[go];

    __shared__ __align__(16) float mT2[K_MERGED * MROW];  // duplicated pairs
    __shared__ __align__(16) float uni[TILE * 132];       // ssm (pad 132) ∪ vecs
    __shared__ float vh[TILE * 50];
    __shared__ float gsig[TILE * 16];
    __shared__ float sWdown[256], sWup[256];

    float* const ssm  = uni;   // [nd*132 + col]
    float* const vecs = uni;   // [nd*52 + c]

    sWdown[t] = W_down[t];
    sWup[t]   = W_up[t];
    __syncthreads();

    const int ntiles = (n_nodes + TILE - 1) / TILE;
    const int acol = t & 127, asub = t >> 7;   // scalar load mapping

    for (int tile = blockIdx.x; tile < ntiles; tile += gridDim.x) {
        const int nb = tile * TILE;

        // ===== Phase A: scalar rows (dup), vecs, sh rows (dup) =====
#pragma unroll 4
        for (int i = 0; i < 16; i++) {
            int nd = asub * 16 + i;
            int node = nb + nd;
            float p = (node < n_nodes) ? scalar[(size_t)node * 128 + acol] : 0.f;
            *reinterpret_cast<float2*>(mT2 + acol * MROW + nd * 2) = make_float2(p, p);
        }
#pragma unroll
        for (int r = 0; r < 2; r++) {
            int idx = t + 256 * r;
            if (idx < 384) {
                int nd = idx / 12, q = idx - nd * 12;
                int node = nb + nd;
                float4 f = (node < n_nodes)
                    ? reinterpret_cast<const float4*>(vector)[(size_t)node * 12 + q]
                    : make_float4(0.f, 0.f, 0.f, 0.f);
                *reinterpret_cast<float4*>(vecs + nd * 52 + q * 4) = f;
            }
        }
        {
            int nd = t & 31, node = nb + nd;
            for (int c = t >> 5; c < 9; c += 8) {
                float v = (node < n_nodes) ? g_fold[(size_t)node * 12 + c] : 0.f;
                *reinterpret_cast<float2*>(mT2 + (144 + c) * MROW + nd * 2) =
                    make_float2(v, v);
            }
        }
        __syncthreads();

        // ===== Phase B: vh + vnorm rows (dup) =====
        {
            int nd = t >> 3, h2 = (t & 7) * 2;
#pragma unroll
            for (int hh = 0; hh < 2; hh++) {
                int h = h2 + hh;
                float a0 = 0.f, a1 = 0.f, a2 = 0.f;
#pragma unroll
                for (int i = 0; i < 16; i++) {
                    float wd = sWdown[h * 16 + i];
                    a0 += vecs[nd * 52 + i * 3 + 0] * wd;
                    a1 += vecs[nd * 52 + i * 3 + 1] * wd;
                    a2 += vecs[nd * 52 + i * 3 + 2] * wd;
                }
                vh[nd * 50 +  0 + h] = a0;
                vh[nd * 50 + 16 + h] = a1;
                vh[nd * 50 + 32 + h] = a2;
                float vn = sqrtf(a0*a0 + a1*a1 + a2*a2 + EPSS);
                *reinterpret_cast<float2*>(mT2 + (128 + h) * MROW + nd * 2) =
                    make_float2(vn, vn);
            }
        }
        __syncthreads();

        // ===== Phase C: zero-MOV outer-product GEMM =====
        {
            unsigned long long a00=0ULL,a01=0ULL,a02=0ULL,a03=0ULL,
                               a10=0ULL,a11=0ULL,a12=0ULL,a13=0ULL;
            const char* wbase = reinterpret_cast<const char*>(g_WsoT + col4);
            const char* mbase = reinterpret_cast<const char*>(mT2 + nd0 * 2);
#pragma unroll 3
            for (int k = 0; k < K_MERGED; k++) {
                ulonglong2 w = *reinterpret_cast<const ulonglong2*>(wbase + (size_t)k * 512);
                ulonglong2 mA = *reinterpret_cast<const ulonglong2*>(mbase + (size_t)k * (MROW*4));
                ulonglong2 mB = *reinterpret_cast<const ulonglong2*>(mbase + (size_t)k * (MROW*4) + 16);
                asm("fma.rn.f32x2 %0, %1, %2, %0;" : "+l"(a00) : "l"(w.x), "l"(mA.x));
                asm("fma.rn.f32x2 %0, %1, %2, %0;" : "+l"(a01) : "l"(w.x), "l"(mA.y));
                asm("fma.rn.f32x2 %0, %1, %2, %0;" : "+l"(a02) : "l"(w.x), "l"(mB.x));
                asm("fma.rn.f32x2 %0, %1, %2, %0;" : "+l"(a03) : "l"(w.x), "l"(mB.y));
                asm("fma.rn.f32x2 %0, %1, %2, %0;" : "+l"(a10) : "l"(w.y), "l"(mA.x));
                asm("fma.rn.f32x2 %0, %1, %2, %0;" : "+l"(a11) : "l"(w.y), "l"(mA.y));
                asm("fma.rn.f32x2 %0, %1, %2, %0;" : "+l"(a12) : "l"(w.y), "l"(mB.x));
                asm("fma.rn.f32x2 %0, %1, %2, %0;" : "+l"(a13) : "l"(w.y), "l"(mB.y));
            }
            // epilogue: acc[cp][j] -> cols (col4+2cp, col4+2cp+1), node nd0+j
            unsigned long long accs[2][4] = {{a00,a01,a02,a03},{a10,a11,a12,a13}};
            float blo[2] = { bso.x, bso.z };
            float bhi[2] = { bso.y, bso.w };
#pragma unroll
            for (int cp = 0; cp < 2; cp++) {
#pragma unroll
                for (int j = 0; j < 4; j++) {
                    float lo, hi;
                    asm("mov.b64 {%0, %1}, %2;" : "=f"(lo), "=f"(hi) : "l"(accs[cp][j]));
                    float sv0 = lo + blo[cp];
                    float sv1 = hi + bhi[cp];
                    float s0 = sv0 / (1.0f + __expf(-sv0));
                    float s1 = sv1 / (1.0f + __expf(-sv1));
                    *reinterpret_cast<float2*>(ssm + (nd0 + j) * 132 + col4 + 2 * cp) =
                        make_float2(s0, s1);
                }
            }
        }
        __syncthreads();

        // ===== Phase D: gates (transposed blocked weights, no shuffles) + out_s =====
        {
            float pA = 0.f, pB = 0.f;
            const float4* wgt = reinterpret_cast<const float4*>(g_WgT + go * 4);
            const float4* sA4 = reinterpret_cast<const float4*>(ssm + ndA * 132);
            const float4* sB4 = reinterpret_cast<const float4*>(ssm + (ndA + 16) * 132);
#pragma unroll 8
            for (int k4 = 0; k4 < 32; k4++) {
                float4 w = __ldg(wgt + k4 * 16);
                float4 xa = sA4[k4];
                float4 xb = sB4[k4];
                pA += w.x*xa.x + w.y*xa.y + w.z*xa.z + w.w*xa.w;
                pB += w.x*xb.x + w.y*xb.y + w.z*xb.z + w.w*xb.w;
            }
            gsig[ndA * 16 + go]        = 1.0f / (1.0f + __expf(-(pA + bg)));
            gsig[(ndA + 16) * 16 + go] = 1.0f / (1.0f + __expf(-(pB + bg)));
        }
#pragma unroll
        for (int r = 0; r < 4; r++) {
            int nd = wid + 8 * r;
            int node = nb + nd;
            float4 v = *reinterpret_cast<const float4*>(ssm + nd * 132 + col4);
            if (node < n_nodes)
                reinterpret_cast<float4*>(out_s + (size_t)node * 128)[lane] = v;
        }
        __syncthreads();

        // ===== Phase E: gated vector output =====
#pragma unroll
        for (int r = 0; r < 6; r++) {
            int i = t + 256 * r;
            int nd = i / 48, j = i - nd * 48;
            int o = j / 3, x = j - o * 3;
            float a = 0.f;
#pragma unroll
            for (int h = 0; h < 16; h++)
                a += vh[nd * 50 + x * 16 + h] * sWup[o * 16 + h];
            int node = nb + nd;
            if (node < n_nodes)
                out_v[(size_t)node * 48 + j] = a * gsig[nd * 16 + o];
        }
        __syncthreads();
    }
}

extern "C" void kernel_launch(void* const* d_in, const int* in_sizes, int n_in,
                              void* d_out, int out_size) {
    const float* scalar = (const float*)d_in[0];
    const float* vector = (const float*)d_in[1];
    const int*   ei     = (const int*)d_in[2];
    const float* frames = (const float*)d_in[3];
    const float* W_down = (const float*)d_in[4];
    const float* W_df   = (const float*)d_in[5];
    const float* W_so   = (const float*)d_in[6];
    const float* b_so   = (const float*)d_in[7];
    const float* W_up   = (const float*)d_in[8];
    const float* W_g    = (const float*)d_in[9];
    const float* b_g    = (const float*)d_in[10];

    int n = in_sizes[0] / S_IN;
    int e = in_sizes[2] / 2;

    float* out_s = (float*)d_out;
    float* out_v = out_s + (size_t)n * S_OUT;

    size_t pre_jobs = (size_t)NREP * n * 4;
    if (pre_jobs < (size_t)n) pre_jobs = n;
    if (pre_jobs < (size_t)K_MERGED * 128) pre_jobs = K_MERGED * 128;

    k_pre<<<(int)((pre_jobs + 255) / 256), 256>>>(vector, W_df, W_so, W_g, n);
    k_edge<<<(e + 255) / 256, 256>>>(ei, frames, e, n);
    k_fold<<<(n + 255) / 256, 256>>>(n);
    k_post<<<444, 256>>>(scalar, vector, W_down, b_so, W_up, b_g,
                         out_s, out_v, n);
}

// round 9
// speedup vs baseline: 1.3433x; 1.1338x over previous
#include <cuda_runtime.h>
#include <math.h>

#define NN_MAX 50000
#define S_IN 128
#define S_OUT 128
#define K_MERGED 153
#define EPSS 1e-8f
#define NREP 8
#define TILE 32
#define MROW 36   // mT2 row (32 nodes + 4 pad), 144B = 16B-aligned

// Scratch (static device globals)
__device__ float g_vdf[NN_MAX * 12];
__device__ float g_acc[(size_t)NREP * NN_MAX * 16];
__device__ float g_fold[NN_MAX * 12];
__device__ float g_WsoT[K_MERGED * 128];   // [k][col]
__device__ float g_WgT[128 * 16];          // blocked: [k4][o][kk], k=k4*4+kk

// ---------------------------------------------------------------------------
// K1: zero accumulators, compute vdf, transpose W_so and W_g
// ---------------------------------------------------------------------------
__global__ void k_pre(const float* __restrict__ vector,
                      const float* __restrict__ W_df,
                      const float* __restrict__ W_so,
                      const float* __restrict__ W_g,
                      int n_nodes)
{
    int tid = blockIdx.x * blockDim.x + threadIdx.x;

    size_t nzero4 = (size_t)NREP * n_nodes * 4;
    if ((size_t)tid < nzero4)
        reinterpret_cast<float4*>(g_acc)[tid] = make_float4(0.f, 0.f, 0.f, 0.f);

    if (tid < K_MERGED * 128) {
        int k = tid >> 7, o = tid & 127;
        g_WsoT[tid] = W_so[o * K_MERGED + k];
    }
    if (tid < 2048) {
        int kk = tid & 3, o = (tid >> 2) & 15, k4 = tid >> 6;
        g_WgT[tid] = W_g[o * 128 + k4 * 4 + kk];
    }

    if (tid >= n_nodes) return;
    int n = tid;

    float v[48];
    const float4* vp = reinterpret_cast<const float4*>(vector + (size_t)n * 48);
#pragma unroll
    for (int q = 0; q < 12; q++) {
        float4 f = vp[q];
        v[q*4+0] = f.x; v[q*4+1] = f.y; v[q*4+2] = f.z; v[q*4+3] = f.w;
    }
#pragma unroll
    for (int j = 0; j < 3; j++) {
        float r0 = 0.f, r1 = 0.f, r2 = 0.f;
#pragma unroll
        for (int i = 0; i < 16; i++) {
            float x = v[i*3 + j];
            r0 += x * __ldg(&W_df[i]);
            r1 += x * __ldg(&W_df[16 + i]);
            r2 += x * __ldg(&W_df[32 + i]);
        }
        g_vdf[(size_t)n*12 + j*3 + 0] = r0;
        g_vdf[(size_t)n*12 + j*3 + 1] = r1;
        g_vdf[(size_t)n*12 + j*3 + 2] = r2;
    }
}

// ---------------------------------------------------------------------------
// K2: per-edge rotation + replicated scatter-add (replica = e & 7)
// ---------------------------------------------------------------------------
__global__ void k_edge(const int* __restrict__ ei,
                       const float* __restrict__ frames,
                       int n_edges, int n_nodes)
{
    int e = blockIdx.x * blockDim.x + threadIdx.x;
    if (e >= n_edges) return;

    int row = ei[e];

    const float4* vp = reinterpret_cast<const float4*>(g_vdf + (size_t)row * 12);
    float4 va = vp[0], vb = vp[1], vc = vp[2];
    float v[9] = { va.x, va.y, va.z, va.w, vb.x, vb.y, vb.z, vb.w, vc.x };

    const float* f = frames + (size_t)e * 9;
    float F[9];
#pragma unroll
    for (int i = 0; i < 9; i++) F[i] = __ldg(&f[i]);

    float loc[9];
#pragma unroll
    for (int x = 0; x < 3; x++)
#pragma unroll
        for (int c = 0; c < 3; c++)
            loc[c*3 + x] = F[x*3+0]*v[0+c] + F[x*3+1]*v[3+c] + F[x*3+2]*v[6+c];

    int rep = e & (NREP - 1);
    float* dst = g_acc + ((size_t)rep * n_nodes + row) * 16;
    asm volatile("red.global.add.v4.f32 [%0], {%1,%2,%3,%4};" ::
                 "l"(dst), "f"(loc[0]), "f"(loc[1]), "f"(loc[2]), "f"(loc[3]) : "memory");
    asm volatile("red.global.add.v4.f32 [%0], {%1,%2,%3,%4};" ::
                 "l"(dst+4), "f"(loc[4]), "f"(loc[5]), "f"(loc[6]), "f"(loc[7]) : "memory");
    asm volatile("red.global.add.v2.f32 [%0], {%1,%2};" ::
                 "l"(dst+8), "f"(loc[8]), "f"(1.0f) : "memory");
}

// ---------------------------------------------------------------------------
// K2b: fold replicas -> meaned 9 values per node
// ---------------------------------------------------------------------------
__global__ void k_fold(int n_nodes)
{
    int n = blockIdx.x * blockDim.x + threadIdx.x;
    if (n >= n_nodes) return;

    float sum[9] = {0,0,0,0,0,0,0,0,0};
    float cnt = 0.f;
#pragma unroll
    for (int r = 0; r < NREP; r++) {
        const float* a = g_acc + ((size_t)r * n_nodes + n) * 16;
        float4 p0 = reinterpret_cast<const float4*>(a)[0];
        float4 p1 = reinterpret_cast<const float4*>(a)[1];
        float2 p2 = reinterpret_cast<const float2*>(a)[4];
        sum[0] += p0.x; sum[1] += p0.y; sum[2] += p0.z; sum[3] += p0.w;
        sum[4] += p1.x; sum[5] += p1.y; sum[6] += p1.z; sum[7] += p1.w;
        sum[8] += p2.x; cnt += p2.y;
    }
    float inv = 1.0f / fmaxf(cnt, 1.0f);
    float* o = g_fold + (size_t)n * 12;
#pragma unroll
    for (int c = 0; c < 9; c++) o[c] = sum[c] * inv;
    o[9] = 0.f; o[10] = 0.f; o[11] = 0.f;
}

// ---------------------------------------------------------------------------
// K3: node MLP. 32-node tiles; warp = 64 cols x 8 nodes (2 cols/lane):
// weight LDG.64 (2 wf/warp/k), merged via 16B LDS broadcasts, 2 MOV dup,
// 8 FFMA2/k. 64 regs -> 4 CTAs/SM.
// ---------------------------------------------------------------------------
__global__ __launch_bounds__(256, 4) void k_post(
    const float* __restrict__ scalar, const float* __restrict__ vector,
    const float* __restrict__ W_down, const float* __restrict__ b_so,
    const float* __restrict__ W_up,
    const float* __restrict__ b_g,
    float* __restrict__ out_s, float* __restrict__ out_v, int n_nodes)
{
    const int t = threadIdx.x;
    const int lane = t & 31;
    const int wid = t >> 5;

    // GEMM assignment: 2 cols, 8 nodes
    const int colh = wid & 1;
    const int nd0g = (wid >> 1) * 8;
    const int c0 = colh * 64 + lane * 2;

    const float2 bso2 = *reinterpret_cast<const float2*>(b_so + c0);

    // gates: o = t&15; nodes ndA = t>>4 and ndA+16
    const int go = t & 15;
    const int ndA = t >> 4;
    const float bg = b_g[go];

    __shared__ __align__(16) float mT2[K_MERGED * MROW];  // k-major merged
    __shared__ __align__(16) float uni[TILE * 132];       // ssm (pad 132) ∪ vecs
    __shared__ float vh[TILE * 50];
    __shared__ float gsig[TILE * 16];
    __shared__ float sWdown[256], sWup[256];

    float* const ssm  = uni;   // [nd*132 + col]
    float* const vecs = uni;   // [nd*52 + c]

    sWdown[t] = W_down[t];
    sWup[t]   = W_up[t];
    __syncthreads();

    const int ntiles = (n_nodes + TILE - 1) / TILE;
    const int acol = t >> 1, ahalf = t & 1;    // phase A mapping

    for (int tile = blockIdx.x; tile < ntiles; tile += gridDim.x) {
        const int nb = tile * TILE;

        // ===== Phase A: scalar -> mT2 rows, vecs, sh rows =====
#pragma unroll 4
        for (int i = 0; i < 16; i++) {
            int nd = ahalf * 16 + i;
            int node = nb + nd;
            float p = (node < n_nodes) ? scalar[(size_t)node * 128 + acol] : 0.f;
            mT2[acol * MROW + nd] = p;
        }
#pragma unroll
        for (int r = 0; r < 2; r++) {
            int idx = t + 256 * r;
            if (idx < 384) {
                int nd = idx / 12, q = idx - nd * 12;
                int node = nb + nd;
                float4 f = (node < n_nodes)
                    ? reinterpret_cast<const float4*>(vector)[(size_t)node * 12 + q]
                    : make_float4(0.f, 0.f, 0.f, 0.f);
                *reinterpret_cast<float4*>(vecs + nd * 52 + q * 4) = f;
            }
        }
        {
            int nd = t & 31, node = nb + nd;
            for (int c = t >> 5; c < 9; c += 8) {
                float v = (node < n_nodes) ? g_fold[(size_t)node * 12 + c] : 0.f;
                mT2[(144 + c) * MROW + nd] = v;
            }
        }
        __syncthreads();

        // ===== Phase B: vh + vnorm rows =====
        {
            int nd = t >> 3, h2 = (t & 7) * 2;
#pragma unroll
            for (int hh = 0; hh < 2; hh++) {
                int h = h2 + hh;
                float a0 = 0.f, a1 = 0.f, a2 = 0.f;
#pragma unroll
                for (int i = 0; i < 16; i++) {
                    float wd = sWdown[h * 16 + i];
                    a0 += vecs[nd * 52 + i * 3 + 0] * wd;
                    a1 += vecs[nd * 52 + i * 3 + 1] * wd;
                    a2 += vecs[nd * 52 + i * 3 + 2] * wd;
                }
                vh[nd * 50 +  0 + h] = a0;
                vh[nd * 50 + 16 + h] = a1;
                vh[nd * 50 + 32 + h] = a2;
                mT2[(128 + h) * MROW + nd] = sqrtf(a0*a0 + a1*a1 + a2*a2 + EPSS);
            }
        }
        __syncthreads();

        // ===== Phase C: outer-product GEMM (2 cols x 8 nodes per lane) =====
        {
            unsigned long long a00=0ULL,a01=0ULL,a02=0ULL,a03=0ULL,
                               a10=0ULL,a11=0ULL,a12=0ULL,a13=0ULL;
            const float* wbase = g_WsoT + c0;
            const float* mbase = mT2 + nd0g;
#pragma unroll 3
            for (int k = 0; k < K_MERGED; k++) {
                float2 w = __ldg(reinterpret_cast<const float2*>(wbase + (size_t)k * 128));
                ulonglong2 mA = *reinterpret_cast<const ulonglong2*>(mbase + (size_t)k * MROW);
                ulonglong2 mB = *reinterpret_cast<const ulonglong2*>(mbase + (size_t)k * MROW + 4);
                unsigned long long wd0, wd1;
                asm("mov.b64 %0, {%1, %1};" : "=l"(wd0) : "f"(w.x));
                asm("mov.b64 %0, {%1, %1};" : "=l"(wd1) : "f"(w.y));
                asm("fma.rn.f32x2 %0, %1, %2, %0;" : "+l"(a00) : "l"(wd0), "l"(mA.x));
                asm("fma.rn.f32x2 %0, %1, %2, %0;" : "+l"(a01) : "l"(wd0), "l"(mA.y));
                asm("fma.rn.f32x2 %0, %1, %2, %0;" : "+l"(a02) : "l"(wd0), "l"(mB.x));
                asm("fma.rn.f32x2 %0, %1, %2, %0;" : "+l"(a03) : "l"(wd0), "l"(mB.y));
                asm("fma.rn.f32x2 %0, %1, %2, %0;" : "+l"(a10) : "l"(wd1), "l"(mA.x));
                asm("fma.rn.f32x2 %0, %1, %2, %0;" : "+l"(a11) : "l"(wd1), "l"(mA.y));
                asm("fma.rn.f32x2 %0, %1, %2, %0;" : "+l"(a12) : "l"(wd1), "l"(mB.x));
                asm("fma.rn.f32x2 %0, %1, %2, %0;" : "+l"(a13) : "l"(wd1), "l"(mB.y));
            }
            // epilogue: acc[c][p] halves = nodes (nd0g+2p, nd0g+2p+1), col c0+c
            unsigned long long acc0[4] = {a00,a01,a02,a03};
            unsigned long long acc1[4] = {a10,a11,a12,a13};
#pragma unroll
            for (int p = 0; p < 4; p++) {
                float lo0, hi0, lo1, hi1;
                asm("mov.b64 {%0, %1}, %2;" : "=f"(lo0), "=f"(hi0) : "l"(acc0[p]));
                asm("mov.b64 {%0, %1}, %2;" : "=f"(lo1), "=f"(hi1) : "l"(acc1[p]));
                float sv00 = lo0 + bso2.x, sv01 = lo1 + bso2.y;
                float sv10 = hi0 + bso2.x, sv11 = hi1 + bso2.y;
                float s00 = sv00 / (1.0f + __expf(-sv00));
                float s01 = sv01 / (1.0f + __expf(-sv01));
                float s10 = sv10 / (1.0f + __expf(-sv10));
                float s11 = sv11 / (1.0f + __expf(-sv11));
                *reinterpret_cast<float2*>(ssm + (nd0g + 2*p    ) * 132 + c0) =
                    make_float2(s00, s01);
                *reinterpret_cast<float2*>(ssm + (nd0g + 2*p + 1) * 132 + c0) =
                    make_float2(s10, s11);
            }
        }
        __syncthreads();

        // ===== Phase D: gates (blocked transposed weights) + out_s =====
        {
            float pA = 0.f, pB = 0.f;
            const float4* wgt = reinterpret_cast<const float4*>(g_WgT + go * 4);
            const float4* sA4 = reinterpret_cast<const float4*>(ssm + ndA * 132);
            const float4* sB4 = reinterpret_cast<const float4*>(ssm + (ndA + 16) * 132);
#pragma unroll 8
            for (int k4 = 0; k4 < 32; k4++) {
                float4 w = __ldg(wgt + k4 * 16);
                float4 xa = sA4[k4];
                float4 xb = sB4[k4];
                pA += w.x*xa.x + w.y*xa.y + w.z*xa.z + w.w*xa.w;
                pB += w.x*xb.x + w.y*xb.y + w.z*xb.z + w.w*xb.w;
            }
            gsig[ndA * 16 + go]        = 1.0f / (1.0f + __expf(-(pA + bg)));
            gsig[(ndA + 16) * 16 + go] = 1.0f / (1.0f + __expf(-(pB + bg)));
        }
#pragma unroll
        for (int r = 0; r < 4; r++) {
            int nd = wid + 8 * r;
            int node = nb + nd;
            float4 v = *reinterpret_cast<const float4*>(ssm + nd * 132 + lane * 4);
            if (node < n_nodes)
                reinterpret_cast<float4*>(out_s + (size_t)node * 128)[lane] = v;
        }
        __syncthreads();

        // ===== Phase E: gated vector output =====
#pragma unroll
        for (int r = 0; r < 6; r++) {
            int i = t + 256 * r;
            int nd = i / 48, j = i - nd * 48;
            int o = j / 3, x = j - o * 3;
            float a = 0.f;
#pragma unroll
            for (int h = 0; h < 16; h++)
                a += vh[nd * 50 + x * 16 + h] * sWup[o * 16 + h];
            int node = nb + nd;
            if (node < n_nodes)
                out_v[(size_t)node * 48 + j] = a * gsig[nd * 16 + o];
        }
        __syncthreads();
    }
}

extern "C" void kernel_launch(void* const* d_in, const int* in_sizes, int n_in,
                              void* d_out, int out_size) {
    const float* scalar = (const float*)d_in[0];
    const float* vector = (const float*)d_in[1];
    const int*   ei     = (const int*)d_in[2];
    const float* frames = (const float*)d_in[3];
    const float* W_down = (const float*)d_in[4];
    const float* W_df   = (const float*)d_in[5];
    const float* W_so   = (const float*)d_in[6];
    const float* b_so   = (const float*)d_in[7];
    const float* W_up   = (const float*)d_in[8];
    const float* W_g    = (const float*)d_in[9];
    const float* b_g    = (const float*)d_in[10];

    int n = in_sizes[0] / S_IN;
    int e = in_sizes[2] / 2;

    float* out_s = (float*)d_out;
    float* out_v = out_s + (size_t)n * S_OUT;

    size_t pre_jobs = (size_t)NREP * n * 4;
    if (pre_jobs < (size_t)n) pre_jobs = n;
    if (pre_jobs < (size_t)K_MERGED * 128) pre_jobs = K_MERGED * 128;

    k_pre<<<(int)((pre_jobs + 255) / 256), 256>>>(vector, W_df, W_so, W_g, n);
    k_edge<<<(e + 255) / 256, 256>>>(ei, frames, e, n);
    k_fold<<<(n + 255) / 256, 256>>>(n);
    k_post<<<592, 256>>>(scalar, vector, W_down, b_so, W_up, b_g,
                         out_s, out_v, n);
}